// round 16
// baseline (speedup 1.0000x reference)
#include <cuda_runtime.h>
#include <cuda_fp16.h>
#include <math.h>
#include <stdint.h>

#define BB 2
#define TT 2048
#define CC 1024
#define HH 16
#define DD 64
#define MM (BB*TT)   // 4096 rows

#define NEG_BIG (-3.0e38f)

// Scratch (allocation-free rule: __device__ globals)
// fp16, k-permuted within 32-element groups (fp16 m16n8k16 fragment layout).
__device__ __half g_q[BB*HH*TT*DD];
__device__ __half g_k[BB*HH*TT*DD];
__device__ __half g_v[BB*HH*TT*DD];
__device__ __half g_y[MM*CC];
__device__ __half g_x[MM*CC];
__device__ __half g_wq[CC*CC];
__device__ __half g_wk[CC*CC];
__device__ __half g_wv[CC*CC];
__device__ __half g_wo[CC*CC];

// ---------------------------------------------------------------------------
// helpers
// ---------------------------------------------------------------------------
__device__ __forceinline__ uint32_t pack_h2(float lo, float hi) {
    uint32_t u;
    asm("cvt.rn.f16x2.f32 %0, %1, %2;" : "=r"(u) : "f"(hi), "f"(lo));
    return u;
}

__device__ __forceinline__ void mma_f16(float d[4],
    uint32_t a0, uint32_t a1, uint32_t a2, uint32_t a3,
    uint32_t b0, uint32_t b1)
{
    asm volatile(
        "mma.sync.aligned.m16n8k16.row.col.f32.f16.f16.f32 "
        "{%0,%1,%2,%3},{%4,%5,%6,%7},{%8,%9},{%0,%1,%2,%3};"
        : "+f"(d[0]), "+f"(d[1]), "+f"(d[2]), "+f"(d[3])
        : "r"(a0), "r"(a1), "r"(a2), "r"(a3), "r"(b0), "r"(b1));
}

__device__ __forceinline__ void ldmx4_trans(
    uint32_t& r0, uint32_t& r1, uint32_t& r2, uint32_t& r3, uint32_t addr)
{
    asm volatile(
        "ldmatrix.sync.aligned.m8n8.x4.trans.shared.b16 {%0,%1,%2,%3}, [%4];"
        : "=r"(r0), "=r"(r1), "=r"(r2), "=r"(r3) : "r"(addr));
}

__device__ __forceinline__ uint32_t smem_to_u32(const void* p) {
    uint32_t a;
    asm("{ .reg .u64 t; cvta.to.shared.u64 t, %1; cvt.u32.u64 %0, t; }"
        : "=r"(a) : "l"(p));
    return a;
}

__device__ __forceinline__ void cp_async16(uint32_t dst, const void* src) {
    asm volatile("cp.async.cg.shared.global [%0], [%1], 16;" :: "r"(dst), "l"(src));
}
#define CP_COMMIT() asm volatile("cp.async.commit_group;" ::: "memory")
#define CP_WAIT(n)  asm volatile("cp.async.wait_group %0;" :: "n"(n) : "memory")

// ---------------------------------------------------------------------------
// prep: convert fp32 -> fp16 (rn) AND permute (pos32 within 32-groups).
// ---------------------------------------------------------------------------
#define NXG32 (MM*CC/32)     // 131072
#define NWG32 (CC*CC/32)     // 32768
__global__ __launch_bounds__(256) void prep_kernel(
    const float* __restrict__ x,
    const float* __restrict__ Wk, const float* __restrict__ Wq,
    const float* __restrict__ Wv, const float* __restrict__ Wo)
{
    int idx = blockIdx.x*blockDim.x + threadIdx.x;
    const float* src; __half* dst; int gi;
    if (idx < NXG32)             { src = x;  dst = g_x;  gi = idx; }
    else if (idx < NXG32+NWG32)  { src = Wq; dst = g_wq; gi = idx - NXG32; }
    else if (idx < NXG32+2*NWG32){ src = Wk; dst = g_wk; gi = idx - NXG32 - NWG32; }
    else if (idx < NXG32+3*NWG32){ src = Wv; dst = g_wv; gi = idx - NXG32 - 2*NWG32; }
    else                         { src = Wo; dst = g_wo; gi = idx - NXG32 - 3*NWG32; }

    float v[32];
    const float4* s4 = (const float4*)(src + (size_t)gi*32);
    #pragma unroll
    for (int i = 0; i < 8; i++) {
        float4 t = s4[i];
        v[i*4+0] = t.x; v[i*4+1] = t.y; v[i*4+2] = t.z; v[i*4+3] = t.w;
    }
    uint4* d4 = (uint4*)(dst + (size_t)gi*32);
    #pragma unroll
    for (int c = 0; c < 4; c++) {
        uint4 o;
        o.x = pack_h2(v[2*c],      v[2*c+1]);
        o.y = pack_h2(v[2*c+8],    v[2*c+9]);
        o.z = pack_h2(v[2*c+16],   v[2*c+17]);
        o.w = pack_h2(v[2*c+24],   v[2*c+25]);
        d4[c] = o;
    }
}

// ---------------------------------------------------------------------------
// GEMM mainloop (R11/R13 config — measured best): out[m,n]=sum_k A[m,k]W[n,k],
// fp16 mma.sync, cp.async. BM=128, BN=64, BK=32 halves, 128 threads = 4 warps
// (2m x 2n), warp tile 64x32. 4-stage ring, 2 stages per sync pair.
// ---------------------------------------------------------------------------
#define S_STAGES 4
#define A_STAGE_B 8192
#define STAGE_B   12288
#define GEMM_SMEM (S_STAGES*STAGE_B)   // 49152
#define KITER (CC/32)                  // 32

__device__ __forceinline__ void gemm_loads(
    uint32_t su, int slot, const __half* Ab, const __half* Wb, int k0, int t)
{
    uint32_t base = su + slot*STAGE_B;
    #pragma unroll
    for (int j = 0; j < 4; j++) {
        int id = t + j*128;
        int r = id >> 2, ch = id & 3;
        cp_async16(base + r*64 + ((ch ^ (r & 3)) << 4),
                   Ab + (size_t)r*CC + k0 + ch*8);
    }
    #pragma unroll
    for (int j = 0; j < 2; j++) {
        int id = t + j*128;
        int r = id >> 2, ch = id & 3;
        cp_async16(base + A_STAGE_B + r*64 + ((ch ^ (r & 3)) << 4),
                   Wb + (size_t)r*CC + k0 + ch*8);
    }
}

__device__ __forceinline__ void gemm_main(
    const __half* __restrict__ A, const __half* __restrict__ W,
    int bm, int bn, char* sm, float acc[4][4][4])
{
    int t = threadIdx.x;
    int lane = t & 31, warp = t >> 5;
    int wm = warp >> 1, wn = warp & 1;
    int g = lane >> 2, t4 = lane & 3;
    uint32_t su = smem_to_u32(sm);

    const __half* Ab = A + (size_t)bm*128*CC;
    const __half* Wb = W + (size_t)bn*64*CC;

    #pragma unroll
    for (int s = 0; s < S_STAGES; s++) {
        gemm_loads(su, s, Ab, Wb, s*32, t);
        CP_COMMIT();
    }

    for (int i = 0; i < KITER; i += 2) {
        CP_WAIT(2);
        __syncthreads();
        #pragma unroll
        for (int u = 0; u < 2; u++) {
            char* Ap = sm + ((i + u) & (S_STAGES-1))*STAGE_B;
            char* Bp = Ap + A_STAGE_B;

            uint4 wa[4], wa8[4], wb[4];
            #pragma unroll
            for (int mf = 0; mf < 4; mf++) {
                int r0 = wm*64 + mf*16 + g;
                int sw = (t4 ^ (r0 & 3)) << 4;
                wa[mf]  = *(const uint4*)(Ap + r0*64 + sw);
                wa8[mf] = *(const uint4*)(Ap + (r0+8)*64 + sw);
            }
            #pragma unroll
            for (int nf = 0; nf < 4; nf++) {
                int rb = wn*32 + nf*8 + g;
                wb[nf] = *(const uint4*)(Bp + rb*64 + ((t4 ^ (rb & 3)) << 4));
            }
            #pragma unroll
            for (int mf = 0; mf < 4; mf++)
                #pragma unroll
                for (int nf = 0; nf < 4; nf++) {
                    mma_f16(acc[mf][nf], wa[mf].x, wa8[mf].x, wa[mf].y, wa8[mf].y,
                            wb[nf].x, wb[nf].y);
                    mma_f16(acc[mf][nf], wa[mf].z, wa8[mf].z, wa[mf].w, wa8[mf].w,
                            wb[nf].z, wb[nf].w);
                }
        }
        __syncthreads();
        if (i + S_STAGES < KITER)
            gemm_loads(su, i & (S_STAGES-1), Ab, Wb, (i+S_STAGES)*32, t);
        CP_COMMIT();
        if (i + S_STAGES + 1 < KITER)
            gemm_loads(su, (i+1) & (S_STAGES-1), Ab, Wb, (i+S_STAGES+1)*32, t);
        CP_COMMIT();
    }
}

// QKV projection. Output scattered to [B,H,T,D], d-columns pos32-permuted fp16.
__global__ __launch_bounds__(128, 4) void qkv_mma_kernel(
    const float* __restrict__ bq,
    const float* __restrict__ bk,
    const float* __restrict__ bv)
{
    extern __shared__ __align__(128) char smem[];
    int bn = blockIdx.x, bm = blockIdx.y, z = blockIdx.z;

    const __half* W; const float* bias; __half* out;
    if (z == 0)      { W = g_wq; bias = bq; out = g_q; }
    else if (z == 1) { W = g_wk; bias = bk; out = g_k; }
    else             { W = g_wv; bias = bv; out = g_v; }

    float acc[4][4][4];
    #pragma unroll
    for (int a = 0; a < 4; a++)
        #pragma unroll
        for (int b = 0; b < 4; b++)
            #pragma unroll
            for (int c = 0; c < 4; c++) acc[a][b][c] = 0.f;

    gemm_main(g_x, W, bm, bn, smem, acc);

    int t = threadIdx.x;
    int lane = t & 31, warp = t >> 5;
    int wm = warp >> 1, wn = warp & 1;
    int g = lane >> 2, t4 = lane & 3;

    int h = bn;   // BN == 64 == D
    #pragma unroll
    for (int nf = 0; nf < 4; nf++) {
        int dloc = wn*32 + nf*8 + 2*t4;
        float b0 = bias[bn*64 + dloc];
        float b1 = bias[bn*64 + dloc + 1];
        int dp0 = wn*32 + 8*t4 + 4*((nf>>1)&1) + 2*(nf&1);
        #pragma unroll
        for (int mf = 0; mf < 4; mf++) {
            int m0 = bm*128 + wm*64 + mf*16 + g;
            int bb0 = m0 >> 11, tt0 = m0 & 2047;
            size_t base0 = (((size_t)bb0*HH + h)*TT + tt0)*DD;
            *(uint32_t*)(out + base0 + dp0) =
                pack_h2(acc[mf][nf][0] + b0, acc[mf][nf][1] + b1);
            int m1 = m0 + 8;
            int bb1 = m1 >> 11, tt1 = m1 & 2047;
            size_t base1 = (((size_t)bb1*HH + h)*TT + tt1)*DD;
            *(uint32_t*)(out + base1 + dp0) =
                pack_h2(acc[mf][nf][2] + b0, acc[mf][nf][3] + b1);
        }
    }
}

// Output projection: A = g_y (fp16 permuted), W = g_wo -> d_out fp32 plain.
__global__ __launch_bounds__(128, 4) void out_mma_kernel(
    const float* __restrict__ bo, float* __restrict__ out)
{
    extern __shared__ __align__(128) char smem[];
    int bn = blockIdx.x, bm = blockIdx.y;

    float acc[4][4][4];
    #pragma unroll
    for (int a = 0; a < 4; a++)
        #pragma unroll
        for (int b = 0; b < 4; b++)
            #pragma unroll
            for (int c = 0; c < 4; c++) acc[a][b][c] = 0.f;

    gemm_main(g_y, g_wo, bm, bn, smem, acc);

    int t = threadIdx.x;
    int lane = t & 31, warp = t >> 5;
    int wm = warp >> 1, wn = warp & 1;
    int g = lane >> 2, t4 = lane & 3;

    #pragma unroll
    for (int nf = 0; nf < 4; nf++) {
        int n = bn*64 + wn*32 + nf*8 + 2*t4;
        float2 bb = *(const float2*)&bo[n];
        #pragma unroll
        for (int mf = 0; mf < 4; mf++) {
            int m0 = bm*128 + wm*64 + mf*16 + g;
            float2 v0 = make_float2(acc[mf][nf][0] + bb.x, acc[mf][nf][1] + bb.y);
            *(float2*)&out[(size_t)m0*CC + n] = v0;
            float2 v1 = make_float2(acc[mf][nf][2] + bb.x, acc[mf][nf][3] + bb.y);
            *(float2*)&out[(size_t)(m0+8)*CC + n] = v1;
        }
    }
}

// ---------------------------------------------------------------------------
// Flash attention (R13 core) + R15 softmax rework:
//  - scores scaled into log2 domain (scale * log2(e)); exp via
//    ex2.approx.f16x2 on the PACKED P fragments (half the MUFU ops; the
//    f32->f16x2 cvt was already needed for the PV A-operand)
//  - row sums l via "ones-MMA": 4 extra mma per sub-tile accumulate exact
//    fp32 row sums of P across all lanes (kills 32 FADD/thread/sub-tile and
//    the epilogue shuffle reduction)
// ---------------------------------------------------------------------------
#define ATTN_SMEM 65536
#define QTILE 128
#define KS_OFF 0
#define VT_OFF 32768
#define SCL2E 0.045084220027779484f   // log2(e) / 32
#define ONES_H2 0x3C003C00u           // (1.0h, 1.0h)

__device__ __forceinline__ void attn_stageK(
    uint32_t su, int buf, const __half* Kg, int kb, int t)
{
    const __half* src = Kg + (size_t)kb*128*DD;
    uint32_t dstb = su + KS_OFF + (uint32_t)buf*16384;
    #pragma unroll
    for (int i = 0; i < 4; i++) {
        int id = t + i*256;
        int j = id >> 3, c = id & 7;
        cp_async16(dstb + 128*j + 16*(c ^ ((j & 1) << 2)), src + j*DD + c*8);
    }
}

__device__ __forceinline__ void attn_stageV(
    uint32_t su, int buf, const __half* Vg, int kb, int t)
{
    const __half* src = Vg + (size_t)kb*128*DD;
    uint32_t dstb = su + VT_OFF + (uint32_t)buf*16384;
    #pragma unroll
    for (int i = 0; i < 4; i++) {
        int id = t + i*256;
        int j = id >> 3, c = id & 7;
        cp_async16(dstb + 128*j + 16*(c ^ (j & 7)), src + j*DD + c*8);
    }
}

__global__ __launch_bounds__(256, 2) void attn_kernel()
{
    extern __shared__ __align__(128) char smc[];

    int qb = gridDim.x - 1 - blockIdx.x;   // heavy blocks first
    int bh = blockIdx.y;
    int t = threadIdx.x;
    int lane = t & 31, w = t >> 5;         // 8 warps
    int g = lane >> 2, t4 = lane & 3;
    uint32_t su = smem_to_u32(smc);

    const __half* Qg = g_q + (size_t)bh*TT*DD + (size_t)qb*QTILE*DD;
    const __half* Kg = g_k + (size_t)bh*TT*DD;
    const __half* Vg = g_v + (size_t)bh*TT*DD;

    // ---- Q fragments in registers ----
    uint4 qA[2][2];
    {
        const __half* q0 = Qg + (w*16 + g)*DD;
        #pragma unroll
        for (int Gv = 0; Gv < 2; Gv++) {
            qA[0][Gv] = *(const uint4*)(q0 + Gv*32 + t4*8);
            qA[1][Gv] = *(const uint4*)(q0 + 8*DD + Gv*32 + t4*8);
        }
    }

    // ldmatrix per-lane geometry
    int gg = lane >> 3, ri = lane & 7;
    int jo = ((gg & 1) << 3) + ri;
    int cshift = gg >> 1;

    int nkt = qb + 1;                      // number of 128-key tiles
    int wrow0 = qb*QTILE + w*16;
    int wrow_max = wrow0 + 15;

    // prologue: stage tile 0 (K + V via cp.async)
    attn_stageK(su, 0, Kg, 0, t);
    attn_stageV(su, 0, Vg, 0, t);
    CP_COMMIT();
    CP_WAIT(0);
    __syncthreads();

    float o[8][4];
    #pragma unroll
    for (int nf = 0; nf < 8; nf++)
        #pragma unroll
        for (int e = 0; e < 4; e++) o[nf][e] = 0.f;
    float lacc[4];
    lacc[0] = lacc[1] = lacc[2] = lacc[3] = 0.f;
    int gx = (g & 1) << 2;

    for (int kb = 0; kb < nkt; kb++) {
        int cur = kb & 1, nxt = cur ^ 1;
        if (kb + 1 < nkt) {
            attn_stageK(su, nxt, Kg, kb+1, t);
            attn_stageV(su, nxt, Vg, kb+1, t);
        }
        CP_COMMIT();

        #pragma unroll
        for (int sub = 0; sub < 2; sub++) {
            int js = kb*128 + sub*64;
            if (js > wrow_max) continue;    // warp entirely before this sub-tile

            // ---- S = Q K^T ----
            float s[8][4];
            #pragma unroll
            for (int nf = 0; nf < 8; nf++)
                #pragma unroll
                for (int e = 0; e < 4; e++) s[nf][e] = 0.f;

            char* Kb = smc + KS_OFF + cur*16384 + sub*8192;
            #pragma unroll
            for (int Gv = 0; Gv < 2; Gv++) {
                uint4 ag  = qA[0][Gv];
                uint4 ag8 = qA[1][Gv];
                #pragma unroll
                for (int nf = 0; nf < 8; nf++) {
                    uint4 wk = *(const uint4*)(Kb + 128*(nf*8 + g)
                                               + 16*(((Gv << 2) | t4) ^ gx));
                    mma_f16(s[nf], ag.x, ag8.x, ag.y, ag8.y, wk.x, wk.y);
                    mma_f16(s[nf], ag.z, ag8.z, ag.w, ag8.w, wk.z, wk.w);
                }
            }

            // ---- log2-domain scale + causal mask ----
            if (js + 63 > wrow0) {
                int i0 = wrow0 + g, i1 = i0 + 8;
                #pragma unroll
                for (int nf = 0; nf < 8; nf++) {
                    #pragma unroll
                    for (int e = 0; e < 2; e++) {
                        int j = js + nf*8 + 2*t4 + e;
                        s[nf][e]   = (j <= i0) ? s[nf][e]*SCL2E   : NEG_BIG;
                        s[nf][2+e] = (j <= i1) ? s[nf][2+e]*SCL2E : NEG_BIG;
                    }
                }
            } else {
                #pragma unroll
                for (int nf = 0; nf < 8; nf++)
                    #pragma unroll
                    for (int e = 0; e < 4; e++) s[nf][e] *= SCL2E;
            }

            // ---- pack to f16x2, exp via ex2.approx.f16x2, l via ones-MMA ----
            uint32_t pp[4][4];
            #pragma unroll
            for (int jg = 0; jg < 4; jg++) {
                pp[jg][0] = pack_h2(s[2*jg][0],   s[2*jg][1]);
                pp[jg][1] = pack_h2(s[2*jg][2],   s[2*jg][3]);
                pp[jg][2] = pack_h2(s[2*jg+1][0], s[2*jg+1][1]);
                pp[jg][3] = pack_h2(s[2*jg+1][2], s[2*jg+1][3]);
                #pragma unroll
                for (int e = 0; e < 4; e++)
                    asm("ex2.approx.f16x2 %0, %0;" : "+r"(pp[jg][e]));
                mma_f16(lacc, pp[jg][0], pp[jg][1], pp[jg][2], pp[jg][3],
                        ONES_H2, ONES_H2);
            }

            // ---- O += P V  (P regs as A; V B-frags via ldmatrix.trans) ----
            uint32_t vb32 = su + VT_OFF + (uint32_t)cur*16384 + (uint32_t)sub*8192;
            #pragma unroll
            for (int jg = 0; jg < 4; jg++) {
                uint32_t rowb = vb32 + (uint32_t)(jg*16 + jo)*128;
                #pragma unroll
                for (int pg = 0; pg < 4; pg++) {
                    uint32_t r0, r1, r2, r3;
                    uint32_t addr = rowb + 16u*(uint32_t)(((pg << 1) + cshift) ^ ri);
                    ldmx4_trans(r0, r1, r2, r3, addr);
                    mma_f16(o[2*pg],   pp[jg][0], pp[jg][1], pp[jg][2], pp[jg][3],
                            r0, r1);
                    mma_f16(o[2*pg+1], pp[jg][0], pp[jg][1], pp[jg][2], pp[jg][3],
                            r2, r3);
                }
            }
        }

        CP_WAIT(0);
        __syncthreads();
    }

    // ---- epilogue: l from ones-MMA accumulators (exact, no shuffles) ----
    float i0v = 1.f / lacc[0], i1v = 1.f / lacc[2];
    int b = bh >> 4, h = bh & 15;
    int q0 = qb*QTILE + w*16 + g;
    int q1 = q0 + 8;
    #pragma unroll
    for (int nf = 0; nf < 8; nf++) {
        int n = nf*8 + 2*t4;   // permuted position label
        *(uint32_t*)(g_y + (size_t)(b*TT + q0)*CC + h*DD + n) =
            pack_h2(o[nf][0]*i0v, o[nf][1]*i0v);
        *(uint32_t*)(g_y + (size_t)(b*TT + q1)*CC + h*DD + n) =
            pack_h2(o[nf][2]*i1v, o[nf][3]*i1v);
    }
}

// ---------------------------------------------------------------------------

extern "C" void kernel_launch(void* const* d_in, const int* in_sizes, int n_in,
                              void* d_out, int out_size)
{
    const float* x  = (const float*)d_in[0];
    const float* Wk = (const float*)d_in[1];
    const float* bk = (const float*)d_in[2];
    const float* Wq = (const float*)d_in[3];
    const float* bq = (const float*)d_in[4];
    const float* Wv = (const float*)d_in[5];
    const float* bv = (const float*)d_in[6];
    const float* Wo = (const float*)d_in[7];
    const float* bo = (const float*)d_in[8];
    float* out = (float*)d_out;

    (void)in_sizes; (void)n_in; (void)out_size;

    cudaFuncSetAttribute(attn_kernel, cudaFuncAttributeMaxDynamicSharedMemorySize,
                         ATTN_SMEM);
    cudaFuncSetAttribute(qkv_mma_kernel, cudaFuncAttributeMaxDynamicSharedMemorySize,
                         GEMM_SMEM);
    cudaFuncSetAttribute(out_mma_kernel, cudaFuncAttributeMaxDynamicSharedMemorySize,
                         GEMM_SMEM);

    // 0) convert+permute inputs to fp16
    {
        int total = NXG32 + 4*NWG32;  // 262144
        prep_kernel<<<total/256, 256>>>(x, Wk, Wq, Wv, Wo);
    }
    // 1) QKV projections
    {
        dim3 grid(CC/64, MM/128, 3);
        qkv_mma_kernel<<<grid, 128, GEMM_SMEM>>>(bq, bk, bv);
    }
    // 2) Causal flash attention
    {
        dim3 grid(TT/QTILE, BB*HH);
        attn_kernel<<<grid, 256, ATTN_SMEM>>>();
    }
    // 3) Output projection
    {
        dim3 grid(CC/64, MM/128);
        out_mma_kernel<<<grid, 128, GEMM_SMEM>>>(bo, out);
    }
}

// round 17
// speedup vs baseline: 1.0524x; 1.0524x over previous
#include <cuda_runtime.h>
#include <cuda_fp16.h>
#include <math.h>
#include <stdint.h>

#define BB 2
#define TT 2048
#define CC 1024
#define HH 16
#define DD 64
#define MM (BB*TT)   // 4096 rows

#define NEG_BIG (-3.0e38f)
#define SCL2E 0.045084220027779484f   // log2(e) / 32  (folded into Wq, bq)

// Scratch (allocation-free rule: __device__ globals)
// fp16, k-permuted within 32-element groups (fp16 m16n8k16 fragment layout).
// g_q (and Wq/bq) carry an extra factor log2(e)/32 so QK^T is log2-domain.
__device__ __half g_q[BB*HH*TT*DD];
__device__ __half g_k[BB*HH*TT*DD];
__device__ __half g_v[BB*HH*TT*DD];
__device__ __half g_y[MM*CC];
__device__ __half g_x[MM*CC];
__device__ __half g_wq[CC*CC];
__device__ __half g_wk[CC*CC];
__device__ __half g_wv[CC*CC];
__device__ __half g_wo[CC*CC];

// ---------------------------------------------------------------------------
// helpers
// ---------------------------------------------------------------------------
__device__ __forceinline__ uint32_t pack_h2(float lo, float hi) {
    uint32_t u;
    asm("cvt.rn.f16x2.f32 %0, %1, %2;" : "=r"(u) : "f"(hi), "f"(lo));
    return u;
}

__device__ __forceinline__ void mma_f16(float d[4],
    uint32_t a0, uint32_t a1, uint32_t a2, uint32_t a3,
    uint32_t b0, uint32_t b1)
{
    asm volatile(
        "mma.sync.aligned.m16n8k16.row.col.f32.f16.f16.f32 "
        "{%0,%1,%2,%3},{%4,%5,%6,%7},{%8,%9},{%0,%1,%2,%3};"
        : "+f"(d[0]), "+f"(d[1]), "+f"(d[2]), "+f"(d[3])
        : "r"(a0), "r"(a1), "r"(a2), "r"(a3), "r"(b0), "r"(b1));
}

__device__ __forceinline__ void ldmx4_trans(
    uint32_t& r0, uint32_t& r1, uint32_t& r2, uint32_t& r3, uint32_t addr)
{
    asm volatile(
        "ldmatrix.sync.aligned.m8n8.x4.trans.shared.b16 {%0,%1,%2,%3}, [%4];"
        : "=r"(r0), "=r"(r1), "=r"(r2), "=r"(r3) : "r"(addr));
}

__device__ __forceinline__ uint32_t smem_to_u32(const void* p) {
    uint32_t a;
    asm("{ .reg .u64 t; cvta.to.shared.u64 t, %1; cvt.u32.u64 %0, t; }"
        : "=r"(a) : "l"(p));
    return a;
}

__device__ __forceinline__ void cp_async16(uint32_t dst, const void* src) {
    asm volatile("cp.async.cg.shared.global [%0], [%1], 16;" :: "r"(dst), "l"(src));
}
#define CP_COMMIT() asm volatile("cp.async.commit_group;" ::: "memory")
#define CP_WAIT(n)  asm volatile("cp.async.wait_group %0;" :: "n"(n) : "memory")

// ---------------------------------------------------------------------------
// prep: convert fp32 -> fp16 (rn) AND permute (pos32 within 32-groups).
// Wq additionally scaled by log2(e)/32 (softmax scale folded into Q).
// ---------------------------------------------------------------------------
#define NXG32 (MM*CC/32)     // 131072
#define NWG32 (CC*CC/32)     // 32768
__global__ __launch_bounds__(256) void prep_kernel(
    const float* __restrict__ x,
    const float* __restrict__ Wk, const float* __restrict__ Wq,
    const float* __restrict__ Wv, const float* __restrict__ Wo)
{
    int idx = blockIdx.x*blockDim.x + threadIdx.x;
    const float* src; __half* dst; int gi; float sc = 1.f;
    if (idx < NXG32)             { src = x;  dst = g_x;  gi = idx; }
    else if (idx < NXG32+NWG32)  { src = Wq; dst = g_wq; gi = idx - NXG32; sc = SCL2E; }
    else if (idx < NXG32+2*NWG32){ src = Wk; dst = g_wk; gi = idx - NXG32 - NWG32; }
    else if (idx < NXG32+3*NWG32){ src = Wv; dst = g_wv; gi = idx - NXG32 - 2*NWG32; }
    else                         { src = Wo; dst = g_wo; gi = idx - NXG32 - 3*NWG32; }

    float v[32];
    const float4* s4 = (const float4*)(src + (size_t)gi*32);
    #pragma unroll
    for (int i = 0; i < 8; i++) {
        float4 t = s4[i];
        v[i*4+0] = t.x*sc; v[i*4+1] = t.y*sc; v[i*4+2] = t.z*sc; v[i*4+3] = t.w*sc;
    }
    uint4* d4 = (uint4*)(dst + (size_t)gi*32);
    #pragma unroll
    for (int c = 0; c < 4; c++) {
        uint4 o;
        o.x = pack_h2(v[2*c],      v[2*c+1]);
        o.y = pack_h2(v[2*c+8],    v[2*c+9]);
        o.z = pack_h2(v[2*c+16],   v[2*c+17]);
        o.w = pack_h2(v[2*c+24],   v[2*c+25]);
        d4[c] = o;
    }
}

// ---------------------------------------------------------------------------
// GEMM mainloop (R11/R13 config — measured best): out[m,n]=sum_k A[m,k]W[n,k],
// fp16 mma.sync, cp.async. BM=128, BN=64, BK=32 halves, 128 threads = 4 warps
// (2m x 2n), warp tile 64x32. 4-stage ring, 2 stages per sync pair.
// ---------------------------------------------------------------------------
#define S_STAGES 4
#define A_STAGE_B 8192
#define STAGE_B   12288
#define GEMM_SMEM (S_STAGES*STAGE_B)   // 49152
#define KITER (CC/32)                  // 32

__device__ __forceinline__ void gemm_loads(
    uint32_t su, int slot, const __half* Ab, const __half* Wb, int k0, int t)
{
    uint32_t base = su + slot*STAGE_B;
    #pragma unroll
    for (int j = 0; j < 4; j++) {
        int id = t + j*128;
        int r = id >> 2, ch = id & 3;
        cp_async16(base + r*64 + ((ch ^ (r & 3)) << 4),
                   Ab + (size_t)r*CC + k0 + ch*8);
    }
    #pragma unroll
    for (int j = 0; j < 2; j++) {
        int id = t + j*128;
        int r = id >> 2, ch = id & 3;
        cp_async16(base + A_STAGE_B + r*64 + ((ch ^ (r & 3)) << 4),
                   Wb + (size_t)r*CC + k0 + ch*8);
    }
}

__device__ __forceinline__ void gemm_main(
    const __half* __restrict__ A, const __half* __restrict__ W,
    int bm, int bn, char* sm, float acc[4][4][4])
{
    int t = threadIdx.x;
    int lane = t & 31, warp = t >> 5;
    int wm = warp >> 1, wn = warp & 1;
    int g = lane >> 2, t4 = lane & 3;
    uint32_t su = smem_to_u32(sm);

    const __half* Ab = A + (size_t)bm*128*CC;
    const __half* Wb = W + (size_t)bn*64*CC;

    #pragma unroll
    for (int s = 0; s < S_STAGES; s++) {
        gemm_loads(su, s, Ab, Wb, s*32, t);
        CP_COMMIT();
    }

    for (int i = 0; i < KITER; i += 2) {
        CP_WAIT(2);
        __syncthreads();
        #pragma unroll
        for (int u = 0; u < 2; u++) {
            char* Ap = sm + ((i + u) & (S_STAGES-1))*STAGE_B;
            char* Bp = Ap + A_STAGE_B;

            uint4 wa[4], wa8[4], wb[4];
            #pragma unroll
            for (int mf = 0; mf < 4; mf++) {
                int r0 = wm*64 + mf*16 + g;
                int sw = (t4 ^ (r0 & 3)) << 4;
                wa[mf]  = *(const uint4*)(Ap + r0*64 + sw);
                wa8[mf] = *(const uint4*)(Ap + (r0+8)*64 + sw);
            }
            #pragma unroll
            for (int nf = 0; nf < 4; nf++) {
                int rb = wn*32 + nf*8 + g;
                wb[nf] = *(const uint4*)(Bp + rb*64 + ((t4 ^ (rb & 3)) << 4));
            }
            #pragma unroll
            for (int mf = 0; mf < 4; mf++)
                #pragma unroll
                for (int nf = 0; nf < 4; nf++) {
                    mma_f16(acc[mf][nf], wa[mf].x, wa8[mf].x, wa[mf].y, wa8[mf].y,
                            wb[nf].x, wb[nf].y);
                    mma_f16(acc[mf][nf], wa[mf].z, wa8[mf].z, wa[mf].w, wa8[mf].w,
                            wb[nf].z, wb[nf].w);
                }
        }
        __syncthreads();
        if (i + S_STAGES < KITER)
            gemm_loads(su, i & (S_STAGES-1), Ab, Wb, (i+S_STAGES)*32, t);
        CP_COMMIT();
        if (i + S_STAGES + 1 < KITER)
            gemm_loads(su, (i+1) & (S_STAGES-1), Ab, Wb, (i+S_STAGES+1)*32, t);
        CP_COMMIT();
    }
}

// QKV projection. Output scattered to [B,H,T,D], d-columns pos32-permuted fp16.
// For z==0 (Q) the bias is scaled by log2(e)/32 to match the scaled Wq.
__global__ __launch_bounds__(128, 4) void qkv_mma_kernel(
    const float* __restrict__ bq,
    const float* __restrict__ bk,
    const float* __restrict__ bv)
{
    extern __shared__ __align__(128) char smem[];
    int bn = blockIdx.x, bm = blockIdx.y, z = blockIdx.z;

    const __half* W; const float* bias; __half* out;
    if (z == 0)      { W = g_wq; bias = bq; out = g_q; }
    else if (z == 1) { W = g_wk; bias = bk; out = g_k; }
    else             { W = g_wv; bias = bv; out = g_v; }
    float bscale = (z == 0) ? SCL2E : 1.f;

    float acc[4][4][4];
    #pragma unroll
    for (int a = 0; a < 4; a++)
        #pragma unroll
        for (int b = 0; b < 4; b++)
            #pragma unroll
            for (int c = 0; c < 4; c++) acc[a][b][c] = 0.f;

    gemm_main(g_x, W, bm, bn, smem, acc);

    int t = threadIdx.x;
    int lane = t & 31, warp = t >> 5;
    int wm = warp >> 1, wn = warp & 1;
    int g = lane >> 2, t4 = lane & 3;

    int h = bn;   // BN == 64 == D
    #pragma unroll
    for (int nf = 0; nf < 4; nf++) {
        int dloc = wn*32 + nf*8 + 2*t4;
        float b0 = bias[bn*64 + dloc] * bscale;
        float b1 = bias[bn*64 + dloc + 1] * bscale;
        int dp0 = wn*32 + 8*t4 + 4*((nf>>1)&1) + 2*(nf&1);
        #pragma unroll
        for (int mf = 0; mf < 4; mf++) {
            int m0 = bm*128 + wm*64 + mf*16 + g;
            int bb0 = m0 >> 11, tt0 = m0 & 2047;
            size_t base0 = (((size_t)bb0*HH + h)*TT + tt0)*DD;
            *(uint32_t*)(out + base0 + dp0) =
                pack_h2(acc[mf][nf][0] + b0, acc[mf][nf][1] + b1);
            int m1 = m0 + 8;
            int bb1 = m1 >> 11, tt1 = m1 & 2047;
            size_t base1 = (((size_t)bb1*HH + h)*TT + tt1)*DD;
            *(uint32_t*)(out + base1 + dp0) =
                pack_h2(acc[mf][nf][2] + b0, acc[mf][nf][3] + b1);
        }
    }
}

// Output projection: A = g_y (fp16 permuted), W = g_wo -> d_out fp32 plain.
__global__ __launch_bounds__(128, 4) void out_mma_kernel(
    const float* __restrict__ bo, float* __restrict__ out)
{
    extern __shared__ __align__(128) char smem[];
    int bn = blockIdx.x, bm = blockIdx.y;

    float acc[4][4][4];
    #pragma unroll
    for (int a = 0; a < 4; a++)
        #pragma unroll
        for (int b = 0; b < 4; b++)
            #pragma unroll
            for (int c = 0; c < 4; c++) acc[a][b][c] = 0.f;

    gemm_main(g_y, g_wo, bm, bn, smem, acc);

    int t = threadIdx.x;
    int lane = t & 31, warp = t >> 5;
    int wm = warp >> 1, wn = warp & 1;
    int g = lane >> 2, t4 = lane & 3;

    #pragma unroll
    for (int nf = 0; nf < 4; nf++) {
        int n = bn*64 + wn*32 + nf*8 + 2*t4;
        float2 bb = *(const float2*)&bo[n];
        #pragma unroll
        for (int mf = 0; mf < 4; mf++) {
            int m0 = bm*128 + wm*64 + mf*16 + g;
            float2 v0 = make_float2(acc[mf][nf][0] + bb.x, acc[mf][nf][1] + bb.y);
            *(float2*)&out[(size_t)m0*CC + n] = v0;
            float2 v1 = make_float2(acc[mf][nf][2] + bb.x, acc[mf][nf][3] + bb.y);
            *(float2*)&out[(size_t)(m0+8)*CC + n] = v1;
        }
    }
}

// ---------------------------------------------------------------------------
// Flash attention (R13 core), fp16 mma.sync m16n8k16. 128-query CTA, 256
// threads = 8 warps; 128-key tiles (two 64-key sub-blocks per barrier round).
// R17: scale folded into Q, so scores come out of QK^T already in log2
// domain — NO per-element FMULs pre-exp; exp = raw ex2.approx.f32.
// V staged via cp.async (natural [j][d], chunk c at c^(j&7)), PV B-fragments
// via ldmatrix.m8n8.x4.trans. Static softmax, P and Q in registers.
// Smem: K 2x16KB + V 2x16KB = 64KB -> 2 CTAs/SM.
// ---------------------------------------------------------------------------
#define ATTN_SMEM 65536
#define QTILE 128
#define KS_OFF 0
#define VT_OFF 32768

__device__ __forceinline__ void attn_stageK(
    uint32_t su, int buf, const __half* Kg, int kb, int t)
{
    const __half* src = Kg + (size_t)kb*128*DD;
    uint32_t dstb = su + KS_OFF + (uint32_t)buf*16384;
    #pragma unroll
    for (int i = 0; i < 4; i++) {
        int id = t + i*256;
        int j = id >> 3, c = id & 7;
        cp_async16(dstb + 128*j + 16*(c ^ ((j & 1) << 2)), src + j*DD + c*8);
    }
}

__device__ __forceinline__ void attn_stageV(
    uint32_t su, int buf, const __half* Vg, int kb, int t)
{
    const __half* src = Vg + (size_t)kb*128*DD;
    uint32_t dstb = su + VT_OFF + (uint32_t)buf*16384;
    #pragma unroll
    for (int i = 0; i < 4; i++) {
        int id = t + i*256;
        int j = id >> 3, c = id & 7;
        cp_async16(dstb + 128*j + 16*(c ^ (j & 7)), src + j*DD + c*8);
    }
}

__global__ __launch_bounds__(256, 2) void attn_kernel()
{
    extern __shared__ __align__(128) char smc[];

    int qb = gridDim.x - 1 - blockIdx.x;   // heavy blocks first
    int bh = blockIdx.y;
    int t = threadIdx.x;
    int lane = t & 31, w = t >> 5;         // 8 warps
    int g = lane >> 2, t4 = lane & 3;
    uint32_t su = smem_to_u32(smc);

    const __half* Qg = g_q + (size_t)bh*TT*DD + (size_t)qb*QTILE*DD;
    const __half* Kg = g_k + (size_t)bh*TT*DD;
    const __half* Vg = g_v + (size_t)bh*TT*DD;

    // ---- Q fragments in registers ----
    uint4 qA[2][2];
    {
        const __half* q0 = Qg + (w*16 + g)*DD;
        #pragma unroll
        for (int Gv = 0; Gv < 2; Gv++) {
            qA[0][Gv] = *(const uint4*)(q0 + Gv*32 + t4*8);
            qA[1][Gv] = *(const uint4*)(q0 + 8*DD + Gv*32 + t4*8);
        }
    }

    // ldmatrix per-lane geometry
    int gg = lane >> 3, ri = lane & 7;
    int jo = ((gg & 1) << 3) + ri;
    int cshift = gg >> 1;

    int nkt = qb + 1;                      // number of 128-key tiles
    int wrow0 = qb*QTILE + w*16;
    int wrow_max = wrow0 + 15;

    // prologue: stage tile 0 (K + V via cp.async)
    attn_stageK(su, 0, Kg, 0, t);
    attn_stageV(su, 0, Vg, 0, t);
    CP_COMMIT();
    CP_WAIT(0);
    __syncthreads();

    float o[8][4];
    #pragma unroll
    for (int nf = 0; nf < 8; nf++)
        #pragma unroll
        for (int e = 0; e < 4; e++) o[nf][e] = 0.f;
    float l0 = 0.f, l1 = 0.f;
    int gx = (g & 1) << 2;

    for (int kb = 0; kb < nkt; kb++) {
        int cur = kb & 1, nxt = cur ^ 1;
        if (kb + 1 < nkt) {
            attn_stageK(su, nxt, Kg, kb+1, t);
            attn_stageV(su, nxt, Vg, kb+1, t);
        }
        CP_COMMIT();

        #pragma unroll
        for (int sub = 0; sub < 2; sub++) {
            int js = kb*128 + sub*64;
            if (js > wrow_max) continue;    // warp entirely before this sub-tile

            // ---- S = Q K^T (already log2-domain: scale folded into Q) ----
            float s[8][4];
            #pragma unroll
            for (int nf = 0; nf < 8; nf++)
                #pragma unroll
                for (int e = 0; e < 4; e++) s[nf][e] = 0.f;

            char* Kb = smc + KS_OFF + cur*16384 + sub*8192;
            #pragma unroll
            for (int Gv = 0; Gv < 2; Gv++) {
                uint4 ag  = qA[0][Gv];
                uint4 ag8 = qA[1][Gv];
                #pragma unroll
                for (int nf = 0; nf < 8; nf++) {
                    uint4 wk = *(const uint4*)(Kb + 128*(nf*8 + g)
                                               + 16*(((Gv << 2) | t4) ^ gx));
                    mma_f16(s[nf], ag.x, ag8.x, ag.y, ag8.y, wk.x, wk.y);
                    mma_f16(s[nf], ag.z, ag8.z, ag.w, ag8.w, wk.z, wk.w);
                }
            }

            // ---- causal mask (only straddling sub-tiles; no scaling) ----
            if (js + 63 > wrow0) {
                int i0 = wrow0 + g, i1 = i0 + 8;
                #pragma unroll
                for (int nf = 0; nf < 8; nf++) {
                    #pragma unroll
                    for (int e = 0; e < 2; e++) {
                        int j = js + nf*8 + 2*t4 + e;
                        if (j > i0) s[nf][e]   = NEG_BIG;
                        if (j > i1) s[nf][2+e] = NEG_BIG;
                    }
                }
            }

            // ---- static softmax: raw ex2 + per-thread partial sums ----
            #pragma unroll
            for (int nf = 0; nf < 8; nf++) {
                asm("ex2.approx.f32 %0, %0;" : "+f"(s[nf][0])); l0 += s[nf][0];
                asm("ex2.approx.f32 %0, %0;" : "+f"(s[nf][1])); l0 += s[nf][1];
                asm("ex2.approx.f32 %0, %0;" : "+f"(s[nf][2])); l1 += s[nf][2];
                asm("ex2.approx.f32 %0, %0;" : "+f"(s[nf][3])); l1 += s[nf][3];
            }

            // ---- O += P V  (P regs as A; V B-frags via ldmatrix.trans) ----
            uint32_t vb32 = su + VT_OFF + (uint32_t)cur*16384 + (uint32_t)sub*8192;
            #pragma unroll
            for (int jg = 0; jg < 4; jg++) {
                uint32_t a0 = pack_h2(s[2*jg][0],   s[2*jg][1]);
                uint32_t a1 = pack_h2(s[2*jg][2],   s[2*jg][3]);
                uint32_t a2 = pack_h2(s[2*jg+1][0], s[2*jg+1][1]);
                uint32_t a3 = pack_h2(s[2*jg+1][2], s[2*jg+1][3]);
                uint32_t rowb = vb32 + (uint32_t)(jg*16 + jo)*128;
                #pragma unroll
                for (int pg = 0; pg < 4; pg++) {
                    uint32_t r0, r1, r2, r3;
                    uint32_t addr = rowb + 16u*(uint32_t)(((pg << 1) + cshift) ^ ri);
                    ldmx4_trans(r0, r1, r2, r3, addr);
                    mma_f16(o[2*pg],   a0, a1, a2, a3, r0, r1);
                    mma_f16(o[2*pg+1], a0, a1, a2, a3, r2, r3);
                }
            }
        }

        CP_WAIT(0);
        __syncthreads();
    }

    // ---- epilogue: reduce l across 4 t4 lanes, normalize, store fp16 ----
    l0 += __shfl_xor_sync(0xffffffffu, l0, 1);
    l0 += __shfl_xor_sync(0xffffffffu, l0, 2);
    l1 += __shfl_xor_sync(0xffffffffu, l1, 1);
    l1 += __shfl_xor_sync(0xffffffffu, l1, 2);
    float i0v = 1.f / l0, i1v = 1.f / l1;
    int b = bh >> 4, h = bh & 15;
    int q0 = qb*QTILE + w*16 + g;
    int q1 = q0 + 8;
    #pragma unroll
    for (int nf = 0; nf < 8; nf++) {
        int n = nf*8 + 2*t4;   // permuted position label
        *(uint32_t*)(g_y + (size_t)(b*TT + q0)*CC + h*DD + n) =
            pack_h2(o[nf][0]*i0v, o[nf][1]*i0v);
        *(uint32_t*)(g_y + (size_t)(b*TT + q1)*CC + h*DD + n) =
            pack_h2(o[nf][2]*i1v, o[nf][3]*i1v);
    }
}

// ---------------------------------------------------------------------------

extern "C" void kernel_launch(void* const* d_in, const int* in_sizes, int n_in,
                              void* d_out, int out_size)
{
    const float* x  = (const float*)d_in[0];
    const float* Wk = (const float*)d_in[1];
    const float* bk = (const float*)d_in[2];
    const float* Wq = (const float*)d_in[3];
    const float* bq = (const float*)d_in[4];
    const float* Wv = (const float*)d_in[5];
    const float* bv = (const float*)d_in[6];
    const float* Wo = (const float*)d_in[7];
    const float* bo = (const float*)d_in[8];
    float* out = (float*)d_out;

    (void)in_sizes; (void)n_in; (void)out_size;

    cudaFuncSetAttribute(attn_kernel, cudaFuncAttributeMaxDynamicSharedMemorySize,
                         ATTN_SMEM);
    cudaFuncSetAttribute(qkv_mma_kernel, cudaFuncAttributeMaxDynamicSharedMemorySize,
                         GEMM_SMEM);
    cudaFuncSetAttribute(out_mma_kernel, cudaFuncAttributeMaxDynamicSharedMemorySize,
                         GEMM_SMEM);

    // 0) convert+permute inputs to fp16 (Wq pre-scaled by log2(e)/32)
    {
        int total = NXG32 + 4*NWG32;  // 262144
        prep_kernel<<<total/256, 256>>>(x, Wk, Wq, Wv, Wo);
    }
    // 1) QKV projections
    {
        dim3 grid(CC/64, MM/128, 3);
        qkv_mma_kernel<<<grid, 128, GEMM_SMEM>>>(bq, bk, bv);
    }
    // 2) Causal flash attention
    {
        dim3 grid(TT/QTILE, BB*HH);
        attn_kernel<<<grid, 256, ATTN_SMEM>>>();
    }
    // 3) Output projection
    {
        dim3 grid(CC/64, MM/128);
        out_mma_kernel<<<grid, 128, GEMM_SMEM>>>(bo, out);
    }
}